// round 3
// baseline (speedup 1.0000x reference)
#include <cuda_runtime.h>

#define BSZ 16
#define SR 16
#define IMW 2048
#define IMH 2048
#define NBX (IMW/BSZ)   // 128
#define NBY (IMH/BSZ)   // 128

#define BPC 4                    // image blocks per CTA (horizontal)
#define NG 3                     // dx groups
#define NJ 11                    // dx per group: 3*11 = 33 exactly, no overlap
#define WINW (BPC*BSZ + 2*SR)    // 96
#define WINH (BSZ + 2*SR)        // 48
#define RST 97                   // ref row stride in pairs; 97*8=776B -> conflict-free 8B loads
#define NTHREADS 416             // 13 warps
#define NITEMS (BPC*NG*33)       // 396
#define IPB (NG*33)              // 99 items per image block

typedef unsigned long long ull;

__device__ __forceinline__ ull f2x_sub(ull a, ull b) {
    ull d; asm("sub.rn.f32x2 %0, %1, %2;" : "=l"(d) : "l"(a), "l"(b)); return d;
}
__device__ __forceinline__ ull f2x_add(ull a, ull b) {
    ull d; asm("add.rn.f32x2 %0, %1, %2;" : "=l"(d) : "l"(a), "l"(b)); return d;
}
__device__ __forceinline__ ull f2x_abs(ull a) {
    return a & 0x7FFFFFFF7FFFFFFFULL;
}
__device__ __forceinline__ ull umin64(ull a, ull b) { return b < a ? b : a; }

__global__ __launch_bounds__(NTHREADS, 2)
void me_sad_kernel(const float* __restrict__ cur,
                   const float* __restrict__ refF,
                   float* __restrict__ out)
{
    // ref window as row-pairs: s_ref[p*RST+c] = (ref[p][c], ref[p+1][c]), p in [0,47)
    __shared__ ull s_ref[(WINH - 1) * RST];                 // 47*97*8 = 36.5 KB
    __shared__ __align__(16) ull s_cur[BPC * 8 * 16];       // 4 KB
    __shared__ ull s_red[NTHREADS];                         // 3.3 KB

    const int t  = threadIdx.x;
    const int cx = blockIdx.x;               // 0..31
    const int by = blockIdx.y;               // 0..127
    const int gx0 = cx * (BPC * BSZ) - SR;
    const int gy0 = by * BSZ - SR;

    // ---- fill ref window (96x48); value feeds .lo of pair-row p and .hi of pair-row p-1
    float* fref = reinterpret_cast<float*>(s_ref);
    for (int i = t; i < WINW * WINH; i += NTHREADS) {
        int pr = i / WINW, pc = i - pr * WINW;
        int gy = gy0 + pr, gx = gx0 + pc;
        float v = 0.0f;
        if ((unsigned)gy < (unsigned)IMH && (unsigned)gx < (unsigned)IMW)
            v = refF[gy * IMW + gx];
        if (pr < WINH - 1) fref[(pr * RST + pc) * 2]           = v;
        if (pr >= 1)       fref[((pr - 1) * RST + pc) * 2 + 1] = v;
    }
    // ---- fill current blocks (4 x 16x16) as row-pairs
    float* fcur = reinterpret_cast<float*>(s_cur);
    for (int i = t; i < BPC * 256; i += NTHREADS) {
        int b = i >> 8;
        int r = (i >> 4) & 15, c = i & 15;
        float v = cur[(by * BSZ + r) * IMW + (cx * BPC + b) * BSZ + c];
        fcur[(b * 128 + (r >> 1) * 16 + c) * 2 + (r & 1)] = v;
    }
    __syncthreads();

    // ---- work item: u = b*99 + g*33 + dyi (pad threads duplicate last item; harmless)
    const int u   = (t < NITEMS) ? t : (NITEMS - 1);
    const int b   = u / IPB;
    const int v0  = u - b * IPB;
    const int g   = v0 / 33;                 // dx = 11g + j - 16, j in [0,10]
    const int dyi = v0 - g * 33;             // 0..32
    const int colbase = b * BSZ + NJ * g;    // leftmost ref pair col for this item

    ull acc[NJ];
    #pragma unroll
    for (int j = 0; j < NJ; j++) acc[j] = 0ULL;

    #pragma unroll 1
    for (int rp = 0; rp < 8; ++rp) {
        ull c2[16];
        const ulonglong2* cp = reinterpret_cast<const ulonglong2*>(&s_cur[b * 128 + rp * 16]);
        #pragma unroll
        for (int k = 0; k < 8; k++) { ulonglong2 w = cp[k]; c2[2*k] = w.x; c2[2*k+1] = w.y; }

        const int prow = rp * 2 + dyi;       // 0..46
        ull r2[16 + NJ - 1];                 // 26 pairs (8B loads: colbase may be odd)
        const ull* rr = &s_ref[prow * RST + colbase];
        #pragma unroll
        for (int k = 0; k < 16 + NJ - 1; k++) r2[k] = rr[k];

        #pragma unroll
        for (int j = 0; j < NJ; j++) {
            ull a = acc[j];
            #pragma unroll
            for (int c = 0; c < 16; c++)
                a = f2x_add(a, f2x_abs(f2x_sub(c2[c], r2[c + j])));
            acc[j] = a;
        }
    }

    // per-thread best, packed (sad_bits << 32) | order_key; u64 min == reference tie rule
    ull p = 0xFFFFFFFFFFFFFFFFULL;
    #pragma unroll
    for (int j = 0; j < NJ; j++) {
        float lo = __uint_as_float((unsigned)(acc[j] & 0xFFFFFFFFu));
        float hi = __uint_as_float((unsigned)(acc[j] >> 32));
        float s = lo + hi;
        unsigned key = (unsigned)(dyi * 33 + NJ * g + j);   // dy-major, dx-minor
        ull cand = ((ull)__float_as_uint(s) << 32) | (ull)key;
        p = umin64(p, cand);
    }
    s_red[t] = p;
    __syncthreads();

    // ---- per-image-block reduction: warp rb reduces items [rb*99, rb*99+99)
    if (t < 128) {
        const int rb = t >> 5;
        const int l  = t & 31;
        const int base = rb * IPB;
        ull best = s_red[base + l];
        best = umin64(best, s_red[base + l + 32]);
        best = umin64(best, s_red[base + l + 64]);
        if (l < IPB - 96) best = umin64(best, s_red[base + l + 96]);
        #pragma unroll
        for (int o = 16; o > 0; o >>= 1) {
            ull q = __shfl_xor_sync(0xFFFFFFFFu, best, o);
            best = umin64(best, q);
        }
        if (l == 0) {
            unsigned key = (unsigned)(best & 0xFFFFFFFFu);
            int dyi_b = key / 33;
            int dxi_b = key - dyi_b * 33;
            int bg = by * NBX + cx * BPC + rb;
            out[bg]                 = (float)(dxi_b - SR);
            out[NBX * NBY + bg]     = (float)(dyi_b - SR);
            out[2 * NBX * NBY + bg] = __uint_as_float((unsigned)(best >> 32));
        }
    }
}

extern "C" void kernel_launch(void* const* d_in, const int* in_sizes, int n_in,
                              void* d_out, int out_size)
{
    const float* c  = (const float*)d_in[0];
    const float* r  = (const float*)d_in[1];
    float* out = (float*)d_out;
    dim3 grid(NBX / BPC, NBY);
    me_sad_kernel<<<grid, NTHREADS>>>(c, r, out);
}

// round 4
// speedup vs baseline: 1.6179x; 1.6179x over previous
#include <cuda_runtime.h>

#define BSZ 16
#define SR 16
#define IMW 2048
#define IMH 2048
#define NBX (IMW/BSZ)   // 128
#define NBY (IMH/BSZ)   // 128

#define BPC 2           // image blocks per CTA (horizontal)
#define WINW (BPC*BSZ + 2*SR)   // 64  ref window width
#define WINH (BSZ + 2*SR)       // 48  ref window height
#define RST 66          // ref row stride in pairs: 66*8=528 B, 528 % 128 == 16 -> conflict-free
#define NTHREADS 288    // 9 full warps
#define NITEMS 272      // 2 blocks x 4 dx-groups x 34 dy-slots

typedef unsigned long long ull;

__device__ __forceinline__ ull f2x_sub(ull a, ull b) {
    ull d; asm("sub.rn.f32x2 %0, %1, %2;" : "=l"(d) : "l"(a), "l"(b)); return d;
}
__device__ __forceinline__ ull f2x_add(ull a, ull b) {
    ull d; asm("add.rn.f32x2 %0, %1, %2;" : "=l"(d) : "l"(a), "l"(b)); return d;
}
__device__ __forceinline__ ull f2x_abs(ull a) {
    return a & 0x7FFFFFFF7FFFFFFFULL;
}
__device__ __forceinline__ ull umin64(ull a, ull b) { return b < a ? b : a; }

__global__ __launch_bounds__(NTHREADS, 3)
void me_sad_kernel(const float* __restrict__ cur,
                   const float* __restrict__ refF,
                   float* __restrict__ out)
{
    // ref window as row-pairs: s_ref[p*RST+c] = (ref[p][c], ref[p+1][c]), p in [0,47)
    __shared__ __align__(16) ull s_ref[47 * RST];          // 24.8 KB
    __shared__ __align__(16) ull s_cur[BPC * 8 * 16];      // 2 KB
    __shared__ ull s_red[NTHREADS];                        // 2.3 KB

    const int t  = threadIdx.x;
    const int cx = blockIdx.x;          // 0..63
    const int by = blockIdx.y;          // 0..127
    const int gx0 = cx * (BPC * BSZ) - SR;
    const int gy0 = by * BSZ - SR;

    // ---- fill ref window (64x48); value feeds .lo of pair-row p and .hi of pair-row p-1
    float* fref = reinterpret_cast<float*>(s_ref);
    for (int i = t; i < WINW * WINH; i += NTHREADS) {
        int pr = i / WINW, pc = i - pr * WINW;
        int gy = gy0 + pr, gx = gx0 + pc;
        float v = 0.0f;
        if ((unsigned)gy < (unsigned)IMH && (unsigned)gx < (unsigned)IMW)
            v = refF[gy * IMW + gx];
        if (pr < WINH - 1) fref[(pr * RST + pc) * 2]           = v;
        if (pr >= 1)       fref[((pr - 1) * RST + pc) * 2 + 1] = v;
    }
    // ---- fill current blocks (2 x 16x16) as row-pairs
    float* fcur = reinterpret_cast<float*>(s_cur);
    for (int i = t; i < BPC * 256; i += NTHREADS) {
        int b = i >> 8;
        int r = (i >> 4) & 15, c = i & 15;
        float v = cur[(by * BSZ + r) * IMW + (cx * BPC + b) * BSZ + c];
        fcur[(b * 128 + (r >> 1) * 16 + c) * 2 + (r & 1)] = v;
    }
    __syncthreads();

    // ---- work item: u = b*136 + g*34 + dyq  (dyq==33 duplicates dyi=32; pad threads dup item 271)
    const int u   = (t < NITEMS) ? t : (NITEMS - 1);
    const int b   = u / 136;
    const int v0  = u - b * 136;
    const int g   = v0 / 34;            // dx group: dx_index = 8g + j, j in [0,8]
    const int dyq = v0 - g * 34;
    const int dyi = (dyq < 33) ? dyq : 32;
    const int colbase = b * BSZ + 8 * g;   // even -> 16B-aligned r2 loads

    ull acc[9];
    #pragma unroll
    for (int j = 0; j < 9; j++) acc[j] = 0ULL;

    #pragma unroll 1
    for (int rp = 0; rp < 8; ++rp) {
        ull c2[16];
        const ulonglong2* cp = reinterpret_cast<const ulonglong2*>(&s_cur[b * 128 + rp * 16]);
        #pragma unroll
        for (int k = 0; k < 8; k++) { ulonglong2 w = cp[k]; c2[2*k] = w.x; c2[2*k+1] = w.y; }

        const int prow = rp * 2 + dyi;   // 0..46
        ull r2[24];
        const ulonglong2* rr = reinterpret_cast<const ulonglong2*>(&s_ref[prow * RST + colbase]);
        #pragma unroll
        for (int k = 0; k < 12; k++) { ulonglong2 w = rr[k]; r2[2*k] = w.x; r2[2*k+1] = w.y; }

        #pragma unroll
        for (int j = 0; j < 9; j++) {
            ull a = acc[j];
            #pragma unroll
            for (int c = 0; c < 16; c++)
                a = f2x_add(a, f2x_abs(f2x_sub(c2[c], r2[c + j])));
            acc[j] = a;
        }
    }

    // per-thread best, packed (sad_bits << 32) | order_key; u64 min == reference tie rule
    ull p = 0xFFFFFFFFFFFFFFFFULL;
    #pragma unroll
    for (int j = 0; j < 9; j++) {
        float lo = __uint_as_float((unsigned)(acc[j] & 0xFFFFFFFFu));
        float hi = __uint_as_float((unsigned)(acc[j] >> 32));
        float s = lo + hi;
        unsigned key = (unsigned)(dyi * 33 + 8 * g + j);   // dy-major, dx-minor canonical order
        ull cand = ((ull)__float_as_uint(s) << 32) | (ull)key;
        p = umin64(p, cand);
    }
    s_red[t] = p;
    __syncthreads();

    // ---- per-image-block reduction: warp 0 -> block 0, warp 1 -> block 1
    if (t < 64) {
        const int rb = t >> 5;
        const int l  = t & 31;
        const int base = rb * 136;
        ull best = s_red[base + l];
        best = umin64(best, s_red[base + l + 32]);
        best = umin64(best, s_red[base + l + 64]);
        best = umin64(best, s_red[base + l + 96]);
        if (l < 8) best = umin64(best, s_red[base + l + 128]);
        #pragma unroll
        for (int o = 16; o > 0; o >>= 1) {
            ull q = __shfl_xor_sync(0xFFFFFFFFu, best, o);
            best = umin64(best, q);
        }
        if (l == 0) {
            unsigned key = (unsigned)(best & 0xFFFFFFFFu);
            int dyi_b = key / 33;
            int dxi_b = key - dyi_b * 33;
            int bg = by * NBX + cx * BPC + rb;
            out[bg]                 = (float)(dxi_b - SR);
            out[NBX * NBY + bg]     = (float)(dyi_b - SR);
            out[2 * NBX * NBY + bg] = __uint_as_float((unsigned)(best >> 32));
        }
    }
}

extern "C" void kernel_launch(void* const* d_in, const int* in_sizes, int n_in,
                              void* d_out, int out_size)
{
    const float* c  = (const float*)d_in[0];
    const float* r  = (const float*)d_in[1];
    float* out = (float*)d_out;
    dim3 grid(NBX / BPC, NBY);
    me_sad_kernel<<<grid, NTHREADS>>>(c, r, out);
}

// round 5
// speedup vs baseline: 1.7118x; 1.0580x over previous
#include <cuda_runtime.h>

#define BSZ 16
#define SR 16
#define IMW 2048
#define IMH 2048
#define NBX (IMW/BSZ)   // 128
#define NBY (IMH/BSZ)   // 128

#define BPC 2                   // image blocks per CTA (horizontal)
#define WINW (BPC*BSZ + 2*SR)   // 64
#define WINH (BSZ + 2*SR)       // 48
#define RST 66                  // ref row stride in pairs: 528 B -> conflict-free
#define NTHREADS 352            // 11 warps
#define J8END 264               // items [0,264): 2 blocks x 4 groups x 33 dy, NJ=8
#define NITEMS 330              // + 66 j1 items (dx=32): [264,330)

typedef unsigned long long ull;

__device__ __forceinline__ ull f2x_sub(ull a, ull b) {
    ull d; asm("sub.rn.f32x2 %0, %1, %2;" : "=l"(d) : "l"(a), "l"(b)); return d;
}
__device__ __forceinline__ ull f2x_add(ull a, ull b) {
    ull d; asm("add.rn.f32x2 %0, %1, %2;" : "=l"(d) : "l"(a), "l"(b)); return d;
}
__device__ __forceinline__ ull f2x_abs(ull a) {
    return a & 0x7FFFFFFF7FFFFFFFULL;
}
__device__ __forceinline__ ull umin64(ull a, ull b) { return b < a ? b : a; }

__device__ __forceinline__ ull sad_pack(ull acc, int key) {
    float lo = __uint_as_float((unsigned)(acc & 0xFFFFFFFFu));
    float hi = __uint_as_float((unsigned)(acc >> 32));
    float s = lo + hi;
    return ((ull)__float_as_uint(s) << 32) | (ull)(unsigned)key;
}

__global__ __launch_bounds__(NTHREADS, 3)
void me_sad_kernel(const float* __restrict__ cur,
                   const float* __restrict__ refF,
                   float* __restrict__ out)
{
    __shared__ __align__(16) ull s_ref[47 * RST];          // 24.8 KB row-pair window
    __shared__ __align__(16) ull s_cur[BPC * 8 * 16];      // 2 KB
    __shared__ ull s_red[NTHREADS];                        // 2.8 KB

    const int t  = threadIdx.x;
    const int cx = blockIdx.x;          // 0..63
    const int by = blockIdx.y;          // 0..127
    const int gx0 = cx * (BPC * BSZ) - SR;
    const int gy0 = by * BSZ - SR;

    // ---- fill ref window (64x48): value feeds .lo of pair-row p and .hi of pair-row p-1
    float* fref = reinterpret_cast<float*>(s_ref);
    for (int i = t; i < WINW * WINH; i += NTHREADS) {
        int pr = i / WINW, pc = i - pr * WINW;
        int gy = gy0 + pr, gx = gx0 + pc;
        float v = 0.0f;
        if ((unsigned)gy < (unsigned)IMH && (unsigned)gx < (unsigned)IMW)
            v = refF[gy * IMW + gx];
        if (pr < WINH - 1) fref[(pr * RST + pc) * 2]           = v;
        if (pr >= 1)       fref[((pr - 1) * RST + pc) * 2 + 1] = v;
    }
    // ---- fill current blocks (2 x 16x16) as row-pairs
    float* fcur = reinterpret_cast<float*>(s_cur);
    for (int i = t; i < BPC * 256; i += NTHREADS) {
        int b = i >> 8;
        int r = (i >> 4) & 15, c = i & 15;
        float v = cur[(by * BSZ + r) * IMW + (cx * BPC + b) * BSZ + c];
        fcur[(b * 128 + (r >> 1) * 16 + c) * 2 + (r & 1)] = v;
    }
    __syncthreads();

    const int u = (t < NITEMS) ? t : (NITEMS - 1);
    ull p = 0xFFFFFFFFFFFFFFFFULL;

    if (u < J8END) {
        // ---- j8 item: u = b*132 + g*33 + dyi ; dx = 8g + j, j in [0,8)
        const int b   = u / 132;
        const int v0  = u - b * 132;
        const int g   = v0 / 33;
        const int dyi = v0 - g * 33;
        const int colbase = b * BSZ + 8 * g;   // even -> 16B-aligned

        ull acc[8];
        #pragma unroll
        for (int j = 0; j < 8; j++) acc[j] = 0ULL;

        #pragma unroll 1
        for (int rp = 0; rp < 8; ++rp) {
            ull c2[16];
            const ulonglong2* cp = reinterpret_cast<const ulonglong2*>(&s_cur[b * 128 + rp * 16]);
            #pragma unroll
            for (int k = 0; k < 8; k++) { ulonglong2 w = cp[k]; c2[2*k] = w.x; c2[2*k+1] = w.y; }

            const int prow = rp * 2 + dyi;
            ull r2[24];   // need 23, load 24 aligned
            const ulonglong2* rr = reinterpret_cast<const ulonglong2*>(&s_ref[prow * RST + colbase]);
            #pragma unroll
            for (int k = 0; k < 12; k++) { ulonglong2 w = rr[k]; r2[2*k] = w.x; r2[2*k+1] = w.y; }

            #pragma unroll
            for (int j = 0; j < 8; j++) {
                ull a = acc[j];
                #pragma unroll
                for (int c = 0; c < 16; c++)
                    a = f2x_add(a, f2x_abs(f2x_sub(c2[c], r2[c + j])));
                acc[j] = a;
            }
        }
        #pragma unroll
        for (int j = 0; j < 8; j++)
            p = umin64(p, sad_pack(acc[j], dyi * 33 + 8 * g + j));
    } else {
        // ---- j1 fixup item (dx = 32): u - J8END = b*33 + dyi
        const int v1  = u - J8END;
        const int b   = v1 / 33;
        const int dyi = v1 - b * 33;
        const int colbase = b * BSZ + 32;      // even

        ull acc = 0ULL;
        #pragma unroll 1
        for (int rp = 0; rp < 8; ++rp) {
            const int prow = rp * 2 + dyi;
            const ulonglong2* cp = reinterpret_cast<const ulonglong2*>(&s_cur[b * 128 + rp * 16]);
            const ulonglong2* rr = reinterpret_cast<const ulonglong2*>(&s_ref[prow * RST + colbase]);
            #pragma unroll
            for (int k = 0; k < 8; k++) {
                ulonglong2 cw = cp[k];
                ulonglong2 rw = rr[k];
                acc = f2x_add(acc, f2x_abs(f2x_sub(cw.x, rw.x)));
                acc = f2x_add(acc, f2x_abs(f2x_sub(cw.y, rw.y)));
            }
        }
        p = sad_pack(acc, dyi * 33 + 32);
    }

    s_red[t] = p;
    __syncthreads();

    // ---- per-image-block reduction: warp rb reduces its block's 165 items
    if (t < 64) {
        const int rb = t >> 5;
        const int l  = t & 31;
        const int base = rb * 132;             // j8 items for this block
        ull best = s_red[base + l];
        best = umin64(best, s_red[base + l + 32]);
        best = umin64(best, s_red[base + l + 64]);
        best = umin64(best, s_red[base + l + 96]);
        if (l < 4)  best = umin64(best, s_red[base + l + 128]);
        const int base2 = J8END + rb * 33;     // j1 items
        if (l < 33 - 32) best = umin64(best, s_red[base2 + l + 32]);
        best = umin64(best, s_red[base2 + l]);
        #pragma unroll
        for (int o = 16; o > 0; o >>= 1) {
            ull q = __shfl_xor_sync(0xFFFFFFFFu, best, o);
            best = umin64(best, q);
        }
        if (l == 0) {
            unsigned key = (unsigned)(best & 0xFFFFFFFFu);
            int dyi_b = key / 33;
            int dxi_b = key - dyi_b * 33;
            int bg = by * NBX + cx * BPC + rb;
            out[bg]                 = (float)(dxi_b - SR);
            out[NBX * NBY + bg]     = (float)(dyi_b - SR);
            out[2 * NBX * NBY + bg] = __uint_as_float((unsigned)(best >> 32));
        }
    }
}

extern "C" void kernel_launch(void* const* d_in, const int* in_sizes, int n_in,
                              void* d_out, int out_size)
{
    const float* c  = (const float*)d_in[0];
    const float* r  = (const float*)d_in[1];
    float* out = (float*)d_out;
    dim3 grid(NBX / BPC, NBY);
    me_sad_kernel<<<grid, NTHREADS>>>(c, r, out);
}

// round 6
// speedup vs baseline: 1.7461x; 1.0200x over previous
#include <cuda_runtime.h>

#define BSZ 16
#define SR 16
#define IMW 2048
#define IMH 2048
#define NBX (IMW/BSZ)   // 128
#define NBY (IMH/BSZ)   // 128

#define BPC 2                   // image blocks per CTA (horizontal)
#define WINW (BPC*BSZ + 2*SR)   // 64
#define WINH (BSZ + 2*SR)       // 48
#define RST 66                  // ref row stride in pairs: 528 B -> conflict-free
#define NTHREADS 352            // 11 warps
#define J8END 264               // items [0,264): 2 blocks x 4 groups x 33 dy, NJ=8
#define NITEMS 330              // + 66 j1 items (dx=32): [264,330)

typedef unsigned long long ull;

__device__ __forceinline__ ull f2x_sub(ull a, ull b) {
    ull d; asm("sub.rn.f32x2 %0, %1, %2;" : "=l"(d) : "l"(a), "l"(b)); return d;
}
__device__ __forceinline__ ull f2x_add(ull a, ull b) {
    ull d; asm("add.rn.f32x2 %0, %1, %2;" : "=l"(d) : "l"(a), "l"(b)); return d;
}
__device__ __forceinline__ ull f2x_abs(ull a) {
    return a & 0x7FFFFFFF7FFFFFFFULL;
}
__device__ __forceinline__ ull umin64(ull a, ull b) { return b < a ? b : a; }

__device__ __forceinline__ ull sad_pack(ull acc, int key) {
    float lo = __uint_as_float((unsigned)(acc & 0xFFFFFFFFu));
    float hi = __uint_as_float((unsigned)(acc >> 32));
    float s = lo + hi;
    return ((ull)__float_as_uint(s) << 32) | (ull)(unsigned)key;
}

__global__ __launch_bounds__(NTHREADS, 2)   // reg cap 93: working set resident
void me_sad_kernel(const float* __restrict__ cur,
                   const float* __restrict__ refF,
                   float* __restrict__ out)
{
    __shared__ __align__(16) ull s_ref[47 * RST];          // 24.8 KB row-pair window
    __shared__ __align__(16) ull s_cur[BPC * 8 * 16];      // 2 KB
    __shared__ ull s_red[NTHREADS];                        // 2.8 KB

    const int t  = threadIdx.x;
    const int cx = blockIdx.x;          // 0..63
    const int by = blockIdx.y;          // 0..127
    const int gx0 = cx * (BPC * BSZ) - SR;
    const int gy0 = by * BSZ - SR;

    // ---- fill ref window (64x48): value feeds .lo of pair-row p and .hi of pair-row p-1
    float* fref = reinterpret_cast<float*>(s_ref);
    for (int i = t; i < WINW * WINH; i += NTHREADS) {
        int pr = i / WINW, pc = i - pr * WINW;
        int gy = gy0 + pr, gx = gx0 + pc;
        float v = 0.0f;
        if ((unsigned)gy < (unsigned)IMH && (unsigned)gx < (unsigned)IMW)
            v = refF[gy * IMW + gx];
        if (pr < WINH - 1) fref[(pr * RST + pc) * 2]           = v;
        if (pr >= 1)       fref[((pr - 1) * RST + pc) * 2 + 1] = v;
    }
    // ---- fill current blocks (2 x 16x16) as row-pairs
    float* fcur = reinterpret_cast<float*>(s_cur);
    for (int i = t; i < BPC * 256; i += NTHREADS) {
        int b = i >> 8;
        int r = (i >> 4) & 15, c = i & 15;
        float v = cur[(by * BSZ + r) * IMW + (cx * BPC + b) * BSZ + c];
        fcur[(b * 128 + (r >> 1) * 16 + c) * 2 + (r & 1)] = v;
    }
    __syncthreads();

    const int u = (t < NITEMS) ? t : (NITEMS - 1);
    ull p = 0xFFFFFFFFFFFFFFFFULL;

    if (u < J8END) {
        // ---- j8 item: u = b*132 + g*33 + dyi ; dx = 8g + j, j in [0,8)
        const int b   = u / 132;
        const int v0  = u - b * 132;
        const int g   = v0 / 33;
        const int dyi = v0 - g * 33;
        const int colbase = b * BSZ + 8 * g;   // even -> 16B-aligned

        ull acc[8];
        #pragma unroll
        for (int j = 0; j < 8; j++) acc[j] = 0ULL;

        #pragma unroll 2
        for (int rp = 0; rp < 8; ++rp) {
            ull c2[16];
            const ulonglong2* cp = reinterpret_cast<const ulonglong2*>(&s_cur[b * 128 + rp * 16]);
            #pragma unroll
            for (int k = 0; k < 8; k++) { ulonglong2 w = cp[k]; c2[2*k] = w.x; c2[2*k+1] = w.y; }

            const int prow = rp * 2 + dyi;
            ull r2[24];   // need 23, load 24 aligned
            const ulonglong2* rr = reinterpret_cast<const ulonglong2*>(&s_ref[prow * RST + colbase]);
            #pragma unroll
            for (int k = 0; k < 12; k++) { ulonglong2 w = rr[k]; r2[2*k] = w.x; r2[2*k+1] = w.y; }

            #pragma unroll
            for (int j = 0; j < 8; j++) {
                ull a = acc[j];
                #pragma unroll
                for (int c = 0; c < 16; c++)
                    a = f2x_add(a, f2x_abs(f2x_sub(c2[c], r2[c + j])));
                acc[j] = a;
            }
        }
        #pragma unroll
        for (int j = 0; j < 8; j++)
            p = umin64(p, sad_pack(acc[j], dyi * 33 + 8 * g + j));
    } else {
        // ---- j1 fixup item (dx = 32): u - J8END = b*33 + dyi
        const int v1  = u - J8END;
        const int b   = v1 / 33;
        const int dyi = v1 - b * 33;
        const int colbase = b * BSZ + 32;      // even

        ull acc = 0ULL;
        #pragma unroll 1
        for (int rp = 0; rp < 8; ++rp) {
            const int prow = rp * 2 + dyi;
            const ulonglong2* cp = reinterpret_cast<const ulonglong2*>(&s_cur[b * 128 + rp * 16]);
            const ulonglong2* rr = reinterpret_cast<const ulonglong2*>(&s_ref[prow * RST + colbase]);
            #pragma unroll
            for (int k = 0; k < 8; k++) {
                ulonglong2 cw = cp[k];
                ulonglong2 rw = rr[k];
                acc = f2x_add(acc, f2x_abs(f2x_sub(cw.x, rw.x)));
                acc = f2x_add(acc, f2x_abs(f2x_sub(cw.y, rw.y)));
            }
        }
        p = sad_pack(acc, dyi * 33 + 32);
    }

    s_red[t] = p;
    __syncthreads();

    // ---- per-image-block reduction: warp rb reduces its block's 165 items
    if (t < 64) {
        const int rb = t >> 5;
        const int l  = t & 31;
        const int base = rb * 132;             // j8 items for this block
        ull best = s_red[base + l];
        best = umin64(best, s_red[base + l + 32]);
        best = umin64(best, s_red[base + l + 64]);
        best = umin64(best, s_red[base + l + 96]);
        if (l < 4)  best = umin64(best, s_red[base + l + 128]);
        const int base2 = J8END + rb * 33;     // j1 items
        if (l < 33 - 32) best = umin64(best, s_red[base2 + l + 32]);
        best = umin64(best, s_red[base2 + l]);
        #pragma unroll
        for (int o = 16; o > 0; o >>= 1) {
            ull q = __shfl_xor_sync(0xFFFFFFFFu, best, o);
            best = umin64(best, q);
        }
        if (l == 0) {
            unsigned key = (unsigned)(best & 0xFFFFFFFFu);
            int dyi_b = key / 33;
            int dxi_b = key - dyi_b * 33;
            int bg = by * NBX + cx * BPC + rb;
            out[bg]                 = (float)(dxi_b - SR);
            out[NBX * NBY + bg]     = (float)(dyi_b - SR);
            out[2 * NBX * NBY + bg] = __uint_as_float((unsigned)(best >> 32));
        }
    }
}

extern "C" void kernel_launch(void* const* d_in, const int* in_sizes, int n_in,
                              void* d_out, int out_size)
{
    const float* c  = (const float*)d_in[0];
    const float* r  = (const float*)d_in[1];
    float* out = (float*)d_out;
    dim3 grid(NBX / BPC, NBY);
    me_sad_kernel<<<grid, NTHREADS>>>(c, r, out);
}